// round 1
// baseline (speedup 1.0000x reference)
#include <cuda_runtime.h>
#include <cstdint>
#include <cstddef>

#define Bsz 4096
#define Tsz 60
#define Dsz 200
#define Hsz 64
#define G4  256
#define BT  (Bsz*Tsz)       // 245760
#define M2  (2*BT)          // 491520

// ---------------- scratch (device globals: allocation-free) ----------------
__device__ float g_XG[(size_t)M2 * G4];          // 503 MB gate pre-activations
__device__ float g_H1[(size_t)M2 * Hsz];         // 126 MB layer-0 hidden seq
__device__ float g_FEAT[(size_t)Bsz * 2 * Tsz * Hsz]; // 126 MB relu(concat) layout
__device__ float g_FC1[(size_t)Bsz * 128];
__device__ float g_PART[240];
__device__ float g_INV[1];

// ---------------- fast (accurate) activations ----------------
__device__ __forceinline__ float fast_sig(float x) {
    return __fdividef(1.0f, 1.0f + __expf(-x));
}
__device__ __forceinline__ float fast_tanh(float x) {
    return 1.0f - __fdividef(2.0f, 1.0f + __expf(2.0f * x));
}

// ---------------- generic fp32 GEMM: C[M,N] = A[M,K] * W[N,K]^T + bias ----------------
// BM=64 fixed, 256 threads, micro-tile TM=8 x TN.
template<int BN, int TN, bool RELU, bool TWOB>
__global__ void __launch_bounds__(256) gemm_nt(
    const float* __restrict__ A, int K,
    const float* __restrict__ W,
    const float* __restrict__ b0, const float* __restrict__ b1,
    float* __restrict__ C, int ldc)
{
    constexpr int BM = 64, BK = 8, TM = 8;
    constexpr int TX = BN / TN;                 // 32
    __shared__ float As[BK][BM];
    __shared__ float Bs[BK][BN];

    const int tid  = threadIdx.x;
    const int tx   = tid % TX;
    const int ty   = tid / TX;
    const int row0 = blockIdx.x * BM;
    const int col0 = blockIdx.y * BN;

    const float* Ab = A + (size_t)row0 * K;
    const float* Wb = W + (size_t)col0 * K;

    const int ar = (2 * tid) >> 3;              // 0..63
    const int ak = (2 * tid) & 7;               // even
    const int bn = tid % BN;
    constexpr int BL = (BN * BK) / 256;         // 8 (BN=256) or 4 (BN=128)
    const int bk0 = (tid / BN) * BL;

    float acc[TM][TN];
#pragma unroll
    for (int i = 0; i < TM; i++)
#pragma unroll
        for (int j = 0; j < TN; j++) acc[i][j] = 0.f;

    for (int k0 = 0; k0 < K; k0 += BK) {
        float2 av = *reinterpret_cast<const float2*>(Ab + (size_t)ar * K + k0 + ak);
        float bt[BL];
#pragma unroll
        for (int i = 0; i < BL; i += 4) {
            float4 v = *reinterpret_cast<const float4*>(Wb + (size_t)bn * K + k0 + bk0 + i);
            bt[i] = v.x; bt[i + 1] = v.y; bt[i + 2] = v.z; bt[i + 3] = v.w;
        }
        As[ak][ar] = av.x;
        As[ak + 1][ar] = av.y;
#pragma unroll
        for (int i = 0; i < BL; i++) Bs[bk0 + i][bn] = bt[i];
        __syncthreads();

#pragma unroll
        for (int kk = 0; kk < BK; kk++) {
            float a[TM], bb[TN];
            float4 a0 = *reinterpret_cast<const float4*>(&As[kk][ty * TM]);
            float4 a1 = *reinterpret_cast<const float4*>(&As[kk][ty * TM + 4]);
            a[0] = a0.x; a[1] = a0.y; a[2] = a0.z; a[3] = a0.w;
            a[4] = a1.x; a[5] = a1.y; a[6] = a1.z; a[7] = a1.w;
#pragma unroll
            for (int j = 0; j < TN; j += 4) {
                float4 b4 = *reinterpret_cast<const float4*>(&Bs[kk][tx * TN + j]);
                bb[j] = b4.x; bb[j + 1] = b4.y; bb[j + 2] = b4.z; bb[j + 3] = b4.w;
            }
#pragma unroll
            for (int i = 0; i < TM; i++)
#pragma unroll
                for (int j = 0; j < TN; j++)
                    acc[i][j] = fmaf(a[i], bb[j], acc[i][j]);
        }
        __syncthreads();
    }

    float bv[TN];
#pragma unroll
    for (int j = 0; j < TN; j++) {
        bv[j] = b0[col0 + tx * TN + j];
        if (TWOB) bv[j] += b1[col0 + tx * TN + j];
    }
#pragma unroll
    for (int i = 0; i < TM; i++) {
        float* Cr = C + (size_t)(row0 + ty * TM + i) * ldc + col0 + tx * TN;
#pragma unroll
        for (int j = 0; j < TN; j += 4) {
            float4 v;
            v.x = acc[i][j + 0] + bv[j + 0];
            v.y = acc[i][j + 1] + bv[j + 1];
            v.z = acc[i][j + 2] + bv[j + 2];
            v.w = acc[i][j + 3] + bv[j + 3];
            if (RELU) {
                v.x = fmaxf(v.x, 0.f); v.y = fmaxf(v.y, 0.f);
                v.z = fmaxf(v.z, 0.f); v.w = fmaxf(v.w, 0.f);
            }
            *reinterpret_cast<float4*>(Cr + j) = v;
        }
    }
}

// ---------------- LSTM recurrence ----------------
// 8 batch rows per CTA, 256 threads. Thread t: row-group rg=t>>7 (rows rg*4..rg*4+3),
// gate columns g0=2*(t&127), g0+1 with W_hh rows held in registers (128 regs).
// h exchanged via shared; c persistent in registers of activation mapping.
// mode 0: out[row*T + t][j]   (H1 layout for layer-1 projection)
// mode 1: out = FEAT[b][inp*T*H + t*H + j] = relu(h)  (concat/reshape layout)
__global__ void __launch_bounds__(256, 1) lstm_rec(
    const float* __restrict__ XG,   // [rows*T, 256]
    const float* __restrict__ Whh,  // [256, 64]
    float* __restrict__ out, int mode)
{
    __shared__ float4 sh_h4[8][16];        // h[8 rows][64]
    __shared__ float  sgate[8][G4];
    float* sh_h = reinterpret_cast<float*>(sh_h4);

    const int tid = threadIdx.x;
    const int rg  = tid >> 7;        // 0..1
    const int cp  = tid & 127;
    const int g0  = 2 * cp;

    float w0[64], w1[64];
    {
        const float4* wp = reinterpret_cast<const float4*>(Whh + (size_t)g0 * Hsz);
#pragma unroll
        for (int i = 0; i < 16; i++) {
            float4 v = wp[i];
            w0[4 * i] = v.x; w0[4 * i + 1] = v.y; w0[4 * i + 2] = v.z; w0[4 * i + 3] = v.w;
        }
#pragma unroll
        for (int i = 0; i < 16; i++) {
            float4 v = wp[16 + i];
            w1[4 * i] = v.x; w1[4 * i + 1] = v.y; w1[4 * i + 2] = v.z; w1[4 * i + 3] = v.w;
        }
    }

    const int row0 = blockIdx.x * 8;
    const float* xgb = XG + ((size_t)(row0 + rg * 4) * Tsz) * G4 + g0;

    // activation mapping: pair A = (ar, aj), pair B = (ar+4, aj)
    const int ar = tid >> 6;   // 0..3
    const int aj = tid & 63;
    float c0 = 0.f, c1 = 0.f;

    sh_h[tid] = 0.f;
    sh_h[tid + 256] = 0.f;
    __syncthreads();

    float2 xc[4];
#pragma unroll
    for (int rr = 0; rr < 4; rr++)
        xc[rr] = *reinterpret_cast<const float2*>(xgb + (size_t)rr * Tsz * G4);

    for (int t = 0; t < Tsz; t++) {
        float2 xn[4];
        const bool more = (t + 1 < Tsz);
        if (more) {
#pragma unroll
            for (int rr = 0; rr < 4; rr++)
                xn[rr] = *reinterpret_cast<const float2*>(
                    xgb + (size_t)rr * Tsz * G4 + (size_t)(t + 1) * G4);
        }

        // gates = xg + h @ Whh^T  (8 FMA per LDS128)
#pragma unroll
        for (int rr = 0; rr < 4; rr++) {
            float a0 = xc[rr].x, a1 = xc[rr].y;
            const float4* hp = sh_h4[rg * 4 + rr];
#pragma unroll
            for (int k = 0; k < 16; k++) {
                float4 hv = hp[k];
                a0 = fmaf(hv.x, w0[4 * k + 0], a0);
                a0 = fmaf(hv.y, w0[4 * k + 1], a0);
                a0 = fmaf(hv.z, w0[4 * k + 2], a0);
                a0 = fmaf(hv.w, w0[4 * k + 3], a0);
                a1 = fmaf(hv.x, w1[4 * k + 0], a1);
                a1 = fmaf(hv.y, w1[4 * k + 1], a1);
                a1 = fmaf(hv.z, w1[4 * k + 2], a1);
                a1 = fmaf(hv.w, w1[4 * k + 3], a1);
            }
            *reinterpret_cast<float2*>(&sgate[rg * 4 + rr][g0]) = make_float2(a0, a1);
        }
        __syncthreads();

        // activations + h writeback (2 (row,j) pairs per thread)
        {
            float iv = sgate[ar][aj], fv = sgate[ar][aj + 64];
            float gv = sgate[ar][aj + 128], ov = sgate[ar][aj + 192];
            c0 = fast_sig(fv) * c0 + fast_sig(iv) * fast_tanh(gv);
            float h = fast_sig(ov) * fast_tanh(c0);
            sh_h[ar * 64 + aj] = h;
            int row = row0 + ar;
            if (mode == 0) {
                out[((size_t)row * Tsz + t) * Hsz + aj] = h;
            } else {
                int inp = row >> 12, b = row & (Bsz - 1);
                out[(size_t)b * (2 * Tsz * Hsz) + (size_t)inp * (Tsz * Hsz)
                    + (size_t)t * Hsz + aj] = fmaxf(h, 0.f);
            }

            int r2 = ar + 4;
            float iv2 = sgate[r2][aj], fv2 = sgate[r2][aj + 64];
            float gv2 = sgate[r2][aj + 128], ov2 = sgate[r2][aj + 192];
            c1 = fast_sig(fv2) * c1 + fast_sig(iv2) * fast_tanh(gv2);
            float h2 = fast_sig(ov2) * fast_tanh(c1);
            sh_h[r2 * 64 + aj] = h2;
            int row2 = row0 + r2;
            if (mode == 0) {
                out[((size_t)row2 * Tsz + t) * Hsz + aj] = h2;
            } else {
                int inp = row2 >> 12, b = row2 & (Bsz - 1);
                out[(size_t)b * (2 * Tsz * Hsz) + (size_t)inp * (Tsz * Hsz)
                    + (size_t)t * Hsz + aj] = fmaxf(h2, 0.f);
            }
        }
        __syncthreads();

        if (more) {
#pragma unroll
            for (int rr = 0; rr < 4; rr++) xc[rr] = xn[rr];
        }
    }
}

// ---------------- FC2 + partial sum-of-squares ----------------
__global__ void __launch_bounds__(256) fc2_norm(
    const float* __restrict__ fc1,   // [B,128]
    const float* __restrict__ w,     // [15,128]
    const float* __restrict__ bias,  // [15]
    float* __restrict__ out,         // [B,15]
    float* __restrict__ partial)
{
    __shared__ float sw[15 * 132];   // padded stride to dodge bank conflicts
    __shared__ float red[256];
    const int tid = threadIdx.x;
    for (int i = tid; i < 15 * 128; i += 256) {
        int n = i >> 7, k = i & 127;
        sw[n * 132 + k] = w[i];
    }
    __syncthreads();

    int idx = blockIdx.x * 256 + tid;          // < 61440
    int b = idx / 15, n = idx - b * 15;
    const float4* fr = reinterpret_cast<const float4*>(fc1 + (size_t)b * 128);
    const float4* wn = reinterpret_cast<const float4*>(sw + n * 132);
    float acc = bias[n];
#pragma unroll
    for (int k = 0; k < 32; k++) {
        float4 f4 = fr[k];
        float4 w4 = wn[k];
        acc = fmaf(f4.x, w4.x, acc);
        acc = fmaf(f4.y, w4.y, acc);
        acc = fmaf(f4.z, w4.z, acc);
        acc = fmaf(f4.w, w4.w, acc);
    }
    out[idx] = acc;
    red[tid] = acc * acc;
    __syncthreads();
#pragma unroll
    for (int s = 128; s > 0; s >>= 1) {
        if (tid < s) red[tid] += red[tid + s];
        __syncthreads();
    }
    if (tid == 0) partial[blockIdx.x] = red[0];
}

__global__ void reduce_norm(const float* __restrict__ partial, float* __restrict__ inv)
{
    __shared__ float red[256];
    float s = 0.f;
    for (int i = threadIdx.x; i < 240; i += 256) s += partial[i];
    red[threadIdx.x] = s;
    __syncthreads();
#pragma unroll
    for (int st = 128; st > 0; st >>= 1) {
        if (threadIdx.x < st) red[threadIdx.x] += red[threadIdx.x + st];
        __syncthreads();
    }
    if (threadIdx.x == 0) inv[0] = 1.0f / sqrtf(red[0]);
}

__global__ void scale_out(float* __restrict__ out, const float* __restrict__ inv)
{
    int i = blockIdx.x * 256 + threadIdx.x;
    out[i] *= inv[0];
}

// ---------------- launch ----------------
extern "C" void kernel_launch(void* const* d_in, const int* in_sizes, int n_in,
                              void* d_out, int out_size)
{
    const float* x1      = (const float*)d_in[0];
    const float* x2      = (const float*)d_in[1];
    const float* W_ih_l0 = (const float*)d_in[2];
    const float* W_hh_l0 = (const float*)d_in[3];
    const float* b_ih_l0 = (const float*)d_in[4];
    const float* b_hh_l0 = (const float*)d_in[5];
    const float* W_ih_l1 = (const float*)d_in[6];
    const float* W_hh_l1 = (const float*)d_in[7];
    const float* b_ih_l1 = (const float*)d_in[8];
    const float* b_hh_l1 = (const float*)d_in[9];
    const float* fc1_w   = (const float*)d_in[10];
    const float* fc1_b   = (const float*)d_in[11];
    const float* fc2_w   = (const float*)d_in[12];
    const float* fc2_b   = (const float*)d_in[13];
    float* out = (float*)d_out;

    float *XG, *H1, *FEAT, *FC1, *PART, *INV;
    cudaGetSymbolAddress((void**)&XG,   g_XG);
    cudaGetSymbolAddress((void**)&H1,   g_H1);
    cudaGetSymbolAddress((void**)&FEAT, g_FEAT);
    cudaGetSymbolAddress((void**)&FC1,  g_FC1);
    cudaGetSymbolAddress((void**)&PART, g_PART);
    cudaGetSymbolAddress((void**)&INV,  g_INV);

    // layer-0 input projection (both sequences)
    gemm_nt<256, 8, false, true><<<dim3(BT / 64, 1), 256>>>(
        x1, Dsz, W_ih_l0, b_ih_l0, b_hh_l0, XG, G4);
    gemm_nt<256, 8, false, true><<<dim3(BT / 64, 1), 256>>>(
        x2, Dsz, W_ih_l0, b_ih_l0, b_hh_l0, XG + (size_t)BT * G4, G4);

    // layer-0 recurrence -> H1
    lstm_rec<<<M2 / (Tsz * 8) * 0 + 1024, 256>>>(XG, W_hh_l0, H1, 0);

    // layer-1 input projection (reuse XG)
    gemm_nt<256, 8, false, true><<<dim3(M2 / 64, 1), 256>>>(
        H1, Hsz, W_ih_l1, b_ih_l1, b_hh_l1, XG, G4);

    // layer-1 recurrence -> relu(FEAT) in concat layout
    lstm_rec<<<1024, 256>>>(XG, W_hh_l1, FEAT, 1);

    // FC1 with fused relu
    gemm_nt<128, 4, true, false><<<dim3(Bsz / 64, 1), 256>>>(
        FEAT, 2 * Tsz * Hsz, fc1_w, fc1_b, nullptr, FC1, 128);

    // FC2 + deterministic norm + scale
    fc2_norm<<<240, 256>>>(FC1, fc2_w, fc2_b, out, PART);
    reduce_norm<<<1, 256>>>(PART, INV);
    scale_out<<<240, 256>>>(out, INV);
}

// round 2
// speedup vs baseline: 1.3518x; 1.3518x over previous
#include <cuda_runtime.h>
#include <cstdint>
#include <cstddef>

#define Bsz 4096
#define Tsz 60
#define Dsz 200
#define Hsz 64
#define G4  256
#define BT  (Bsz*Tsz)       // 245760
#define M2  (2*BT)          // 491520
#define FCK (2*Tsz*Hsz)     // 7680
#define KSPLIT 4
#define KCHUNK (FCK/KSPLIT) // 1920

// ---------------- scratch (device globals: allocation-free) ----------------
__device__ float g_XG[(size_t)M2 * G4];                  // 503 MB gate pre-activations
__device__ float g_H1[(size_t)M2 * Hsz];                 // 126 MB layer-0 hidden seq
__device__ float g_FEAT[(size_t)Bsz * FCK];              // 126 MB relu(concat) layout
__device__ float g_FC1P[(size_t)KSPLIT * Bsz * 128];     // 8 MB split-K partials
__device__ float g_FC1R[(size_t)Bsz * 128];
__device__ float g_PART[240];
__device__ float g_INV[1];

// ---------------- fast (accurate) activations ----------------
__device__ __forceinline__ float fast_sig(float x) {
    return __fdividef(1.0f, 1.0f + __expf(-x));
}
__device__ __forceinline__ float fast_tanh(float x) {
    return 1.0f - __fdividef(2.0f, 1.0f + __expf(2.0f * x));
}

// ---------------- fp32 GEMM: C[M,N] = A[M,K] * W[N,K]^T (+bias) ----------------
// BM=64, 256 threads, TM=8 x TN micro-tile, 2-stage smem double buffering with
// register-staged global loads overlapped with compute (1 sync per K-iter).
// blockIdx.z = K-split index (koff = z*Kloop, C += z*csplit).
template<int BN, int TN, int NB, bool RELU>
__global__ void __launch_bounds__(256) gemm_nt(
    const float* __restrict__ A, int lda, int Kloop,
    const float* __restrict__ W, int ldw,
    const float* __restrict__ b0, const float* __restrict__ b1,
    float* __restrict__ C, int ldc, size_t csplit)
{
    constexpr int BM = 64, BK = 8, TM = 8;
    constexpr int TX = BN / TN;
    constexpr int BL = (BN * BK) / 256;         // 8 (BN=256) or 4 (BN=128)
    __shared__ float As[2][BK][BM];
    __shared__ float Bs[2][BK][BN];

    const int tid  = threadIdx.x;
    const int tx   = tid % TX;
    const int ty   = tid / TX;
    const int row0 = blockIdx.x * BM;
    const int col0 = blockIdx.y * BN;
    const int koff = blockIdx.z * Kloop;

    const float* Ab = A + (size_t)row0 * lda + koff;
    const float* Wb = W + (size_t)col0 * ldw + koff;
    float* Cb = C + (size_t)blockIdx.z * csplit;

    const int ar = (2 * tid) >> 3;              // 0..63
    const int ak = (2 * tid) & 7;               // even
    const int bn = tid % BN;
    const int bk0 = (tid / BN) * BL;

    float acc[TM][TN];
#pragma unroll
    for (int i = 0; i < TM; i++)
#pragma unroll
        for (int j = 0; j < TN; j++) acc[i][j] = 0.f;

    // prologue: load k0=0 into regs, store to buffer 0
    float2 av = *reinterpret_cast<const float2*>(Ab + (size_t)ar * lda + ak);
    float bt[BL];
#pragma unroll
    for (int i = 0; i < BL; i += 4) {
        float4 v = *reinterpret_cast<const float4*>(Wb + (size_t)bn * ldw + bk0 + i);
        bt[i] = v.x; bt[i + 1] = v.y; bt[i + 2] = v.z; bt[i + 3] = v.w;
    }
    As[0][ak][ar] = av.x;
    As[0][ak + 1][ar] = av.y;
#pragma unroll
    for (int i = 0; i < BL; i++) Bs[0][bk0 + i][bn] = bt[i];
    __syncthreads();

    int buf = 0;
    for (int k0 = 0;; k0 += BK) {
        const bool more = (k0 + BK) < Kloop;
        if (more) {
            av = *reinterpret_cast<const float2*>(Ab + (size_t)ar * lda + k0 + BK + ak);
#pragma unroll
            for (int i = 0; i < BL; i += 4) {
                float4 v = *reinterpret_cast<const float4*>(
                    Wb + (size_t)bn * ldw + k0 + BK + bk0 + i);
                bt[i] = v.x; bt[i + 1] = v.y; bt[i + 2] = v.z; bt[i + 3] = v.w;
            }
        }

#pragma unroll
        for (int kk = 0; kk < BK; kk++) {
            float a[TM], bb[TN];
            float4 a0 = *reinterpret_cast<const float4*>(&As[buf][kk][ty * TM]);
            float4 a1 = *reinterpret_cast<const float4*>(&As[buf][kk][ty * TM + 4]);
            a[0] = a0.x; a[1] = a0.y; a[2] = a0.z; a[3] = a0.w;
            a[4] = a1.x; a[5] = a1.y; a[6] = a1.z; a[7] = a1.w;
#pragma unroll
            for (int j = 0; j < TN; j += 4) {
                float4 b4 = *reinterpret_cast<const float4*>(&Bs[buf][kk][tx * TN + j]);
                bb[j] = b4.x; bb[j + 1] = b4.y; bb[j + 2] = b4.z; bb[j + 3] = b4.w;
            }
#pragma unroll
            for (int i = 0; i < TM; i++)
#pragma unroll
                for (int j = 0; j < TN; j++)
                    acc[i][j] = fmaf(a[i], bb[j], acc[i][j]);
        }

        if (!more) break;
        // stage next tile into the other buffer (prev compute on buf^1 finished
        // at the sync that ended the previous iteration)
        As[buf ^ 1][ak][ar] = av.x;
        As[buf ^ 1][ak + 1][ar] = av.y;
#pragma unroll
        for (int i = 0; i < BL; i++) Bs[buf ^ 1][bk0 + i][bn] = bt[i];
        __syncthreads();
        buf ^= 1;
    }

    float bv[TN];
#pragma unroll
    for (int j = 0; j < TN; j++) {
        bv[j] = 0.f;
        if (NB >= 1) bv[j] += b0[col0 + tx * TN + j];
        if (NB >= 2) bv[j] += b1[col0 + tx * TN + j];
    }
#pragma unroll
    for (int i = 0; i < TM; i++) {
        float* Cr = Cb + (size_t)(row0 + ty * TM + i) * ldc + col0 + tx * TN;
#pragma unroll
        for (int j = 0; j < TN; j += 4) {
            float4 v;
            v.x = acc[i][j + 0] + bv[j + 0];
            v.y = acc[i][j + 1] + bv[j + 1];
            v.z = acc[i][j + 2] + bv[j + 2];
            v.w = acc[i][j + 3] + bv[j + 3];
            if (RELU) {
                v.x = fmaxf(v.x, 0.f); v.y = fmaxf(v.y, 0.f);
                v.z = fmaxf(v.z, 0.f); v.w = fmaxf(v.w, 0.f);
            }
            *reinterpret_cast<float4*>(Cr + j) = v;
        }
    }
}

// ---------------- LSTM recurrence ----------------
// 4 batch rows per CTA, 256 threads, 2 CTAs/SM. Thread t owns gate column g=t
// (Whh row in 64 registers) and computes it for all 4 rows; activation phase
// remaps thread -> (row t>>6, hidden t&63) with c persistent in a register.
// mode 0: out[row*T + t][j]   (H1 layout for layer-1 projection)
// mode 1: out = FEAT[b][inp*T*H + t*H + j] = relu(h)  (concat/reshape layout)
__global__ void __launch_bounds__(256, 2) lstm_rec(
    const float* __restrict__ XG,   // [rows*T, 256]
    const float* __restrict__ Whh,  // [256, 64]
    float* __restrict__ out, int mode)
{
    __shared__ float4 sh_h4[4][16];        // h[4 rows][64]
    __shared__ float  sgate[4][G4];
    float* sh_h = reinterpret_cast<float*>(sh_h4);

    const int tid = threadIdx.x;
    const int g   = tid;

    float w[64];
    {
        const float4* wp = reinterpret_cast<const float4*>(Whh + (size_t)g * Hsz);
#pragma unroll
        for (int i = 0; i < 16; i++) {
            float4 v = wp[i];
            w[4 * i] = v.x; w[4 * i + 1] = v.y; w[4 * i + 2] = v.z; w[4 * i + 3] = v.w;
        }
    }

    const int row0 = blockIdx.x * 4;
    const float* xgb = XG + (size_t)row0 * Tsz * G4 + g;

    const int ar = tid >> 6;   // 0..3
    const int aj = tid & 63;
    float c = 0.f;

    sh_h[tid] = 0.f;           // 4*64 = 256 floats
    __syncthreads();

    float xc[4];
#pragma unroll
    for (int rr = 0; rr < 4; rr++)
        xc[rr] = xgb[(size_t)rr * Tsz * G4];

    for (int t = 0; t < Tsz; t++) {
        float xn[4];
        const bool more = (t + 1 < Tsz);
        if (more) {
#pragma unroll
            for (int rr = 0; rr < 4; rr++)
                xn[rr] = xgb[(size_t)rr * Tsz * G4 + (size_t)(t + 1) * G4];
        }

        // gates = xg + h @ Whh^T
#pragma unroll
        for (int rr = 0; rr < 4; rr++) {
            float a = xc[rr];
            const float4* hp = sh_h4[rr];
#pragma unroll
            for (int k = 0; k < 16; k++) {
                float4 hv = hp[k];
                a = fmaf(hv.x, w[4 * k + 0], a);
                a = fmaf(hv.y, w[4 * k + 1], a);
                a = fmaf(hv.z, w[4 * k + 2], a);
                a = fmaf(hv.w, w[4 * k + 3], a);
            }
            sgate[rr][g] = a;
        }
        __syncthreads();

        // activations + h writeback (1 (row,j) pair per thread)
        {
            float iv = sgate[ar][aj], fv = sgate[ar][aj + 64];
            float gv = sgate[ar][aj + 128], ov = sgate[ar][aj + 192];
            c = fast_sig(fv) * c + fast_sig(iv) * fast_tanh(gv);
            float h = fast_sig(ov) * fast_tanh(c);
            sh_h[ar * 64 + aj] = h;
            int row = row0 + ar;
            if (mode == 0) {
                out[((size_t)row * Tsz + t) * Hsz + aj] = h;
            } else {
                int inp = row >> 12, b = row & (Bsz - 1);
                out[(size_t)b * FCK + (size_t)inp * (Tsz * Hsz)
                    + (size_t)t * Hsz + aj] = fmaxf(h, 0.f);
            }
        }
        __syncthreads();

#pragma unroll
        for (int rr = 0; rr < 4; rr++) xc[rr] = xn[rr];
    }
}

// ---------------- FC1 split-K reduction (+bias, +relu) ----------------
__global__ void __launch_bounds__(256) fc1_reduce(
    const float* __restrict__ part, const float* __restrict__ bias,
    float* __restrict__ outp)
{
    const size_t S = (size_t)Bsz * 128;
    size_t i = (size_t)blockIdx.x * 256 + threadIdx.x;   // < 524288
    int n = (int)(i & 127);
    float s = bias[n] + part[i] + part[i + S] + part[i + 2 * S] + part[i + 3 * S];
    outp[i] = fmaxf(s, 0.f);
}

// ---------------- FC2 + partial sum-of-squares ----------------
__global__ void __launch_bounds__(256) fc2_norm(
    const float* __restrict__ fc1,   // [B,128]
    const float* __restrict__ w,     // [15,128]
    const float* __restrict__ bias,  // [15]
    float* __restrict__ out,         // [B,15]
    float* __restrict__ partial)
{
    __shared__ float sw[15 * 132];
    __shared__ float red[256];
    const int tid = threadIdx.x;
    for (int i = tid; i < 15 * 128; i += 256) {
        int n = i >> 7, k = i & 127;
        sw[n * 132 + k] = w[i];
    }
    __syncthreads();

    int idx = blockIdx.x * 256 + tid;          // < 61440
    int b = idx / 15, n = idx - b * 15;
    const float4* fr = reinterpret_cast<const float4*>(fc1 + (size_t)b * 128);
    const float4* wn = reinterpret_cast<const float4*>(sw + n * 132);
    float acc = bias[n];
#pragma unroll
    for (int k = 0; k < 32; k++) {
        float4 f4 = fr[k];
        float4 w4 = wn[k];
        acc = fmaf(f4.x, w4.x, acc);
        acc = fmaf(f4.y, w4.y, acc);
        acc = fmaf(f4.z, w4.z, acc);
        acc = fmaf(f4.w, w4.w, acc);
    }
    out[idx] = acc;
    red[tid] = acc * acc;
    __syncthreads();
#pragma unroll
    for (int s = 128; s > 0; s >>= 1) {
        if (tid < s) red[tid] += red[tid + s];
        __syncthreads();
    }
    if (tid == 0) partial[blockIdx.x] = red[0];
}

__global__ void reduce_norm(const float* __restrict__ partial, float* __restrict__ inv)
{
    __shared__ float red[256];
    float s = 0.f;
    for (int i = threadIdx.x; i < 240; i += 256) s += partial[i];
    red[threadIdx.x] = s;
    __syncthreads();
#pragma unroll
    for (int st = 128; st > 0; st >>= 1) {
        if (threadIdx.x < st) red[threadIdx.x] += red[threadIdx.x + st];
        __syncthreads();
    }
    if (threadIdx.x == 0) inv[0] = 1.0f / sqrtf(red[0]);
}

__global__ void scale_out(float* __restrict__ out, const float* __restrict__ inv)
{
    int i = blockIdx.x * 256 + threadIdx.x;
    out[i] *= inv[0];
}

// ---------------- launch ----------------
extern "C" void kernel_launch(void* const* d_in, const int* in_sizes, int n_in,
                              void* d_out, int out_size)
{
    const float* x1      = (const float*)d_in[0];
    const float* x2      = (const float*)d_in[1];
    const float* W_ih_l0 = (const float*)d_in[2];
    const float* W_hh_l0 = (const float*)d_in[3];
    const float* b_ih_l0 = (const float*)d_in[4];
    const float* b_hh_l0 = (const float*)d_in[5];
    const float* W_ih_l1 = (const float*)d_in[6];
    const float* W_hh_l1 = (const float*)d_in[7];
    const float* b_ih_l1 = (const float*)d_in[8];
    const float* b_hh_l1 = (const float*)d_in[9];
    const float* fc1_w   = (const float*)d_in[10];
    const float* fc1_b   = (const float*)d_in[11];
    const float* fc2_w   = (const float*)d_in[12];
    const float* fc2_b   = (const float*)d_in[13];
    float* out = (float*)d_out;

    float *XG, *H1, *FEAT, *FC1P, *FC1R, *PART, *INV;
    cudaGetSymbolAddress((void**)&XG,   g_XG);
    cudaGetSymbolAddress((void**)&H1,   g_H1);
    cudaGetSymbolAddress((void**)&FEAT, g_FEAT);
    cudaGetSymbolAddress((void**)&FC1P, g_FC1P);
    cudaGetSymbolAddress((void**)&FC1R, g_FC1R);
    cudaGetSymbolAddress((void**)&PART, g_PART);
    cudaGetSymbolAddress((void**)&INV,  g_INV);

    // layer-0 input projection (both sequences)
    gemm_nt<256, 8, 2, false><<<dim3(BT / 64, 1, 1), 256>>>(
        x1, Dsz, Dsz, W_ih_l0, Dsz, b_ih_l0, b_hh_l0, XG, G4, 0);
    gemm_nt<256, 8, 2, false><<<dim3(BT / 64, 1, 1), 256>>>(
        x2, Dsz, Dsz, W_ih_l0, Dsz, b_ih_l0, b_hh_l0, XG + (size_t)BT * G4, G4, 0);

    // layer-0 recurrence -> H1
    lstm_rec<<<2048, 256>>>(XG, W_hh_l0, H1, 0);

    // layer-1 input projection (reuse XG)
    gemm_nt<256, 8, 2, false><<<dim3(M2 / 64, 1, 1), 256>>>(
        H1, Hsz, Hsz, W_ih_l1, Hsz, b_ih_l1, b_hh_l1, XG, G4, 0);

    // layer-1 recurrence -> relu(FEAT) in concat layout
    lstm_rec<<<2048, 256>>>(XG, W_hh_l1, FEAT, 1);

    // FC1: split-K x4, deterministic partial buffers, then reduce+bias+relu
    gemm_nt<128, 4, 0, false><<<dim3(Bsz / 64, 1, KSPLIT), 256>>>(
        FEAT, FCK, KCHUNK, fc1_w, FCK, nullptr, nullptr,
        FC1P, 128, (size_t)Bsz * 128);
    fc1_reduce<<<(Bsz * 128) / 256, 256>>>(FC1P, fc1_b, FC1R);

    // FC2 + deterministic norm + scale
    fc2_norm<<<240, 256>>>(FC1R, fc2_w, fc2_b, out, PART);
    reduce_norm<<<1, 256>>>(PART, INV);
    scale_out<<<240, 256>>>(out, INV);
}